// round 16
// baseline (speedup 1.0000x reference)
#include <cuda_runtime.h>
#include <cuda_fp16.h>
#include <cstdint>

#define D 128
#define MAXN 50000
#define MAXE 800000

// Scratch (allocation-free)
__device__ float  g_H[MAXN * D];      // exact fp32 residual H
__device__ float  g_P[MAXN * D];      // fp32 partial (Ht @ w_root)
__device__ __half g_Ht[MAXN * D];     // fp16 H (GEMM A-operand + gather source)
__device__ __half g_AGG[MAXN * D];    // fp16 aggregate (also fp16 x for in_fc)
__device__ __half g_Wh[7 * D * D];    // fp16 weights, transposed [n][k]
__device__ int g_cnt[MAXN];
__device__ int g_row_ptr[MAXN + 1];
__device__ int g_rank[MAXE];
__device__ int g_adj[MAXE];
__device__ int g_bsum[64];
__device__ int g_bofs[64];

// Side stream + events, created at static-init (host objects; before the
// harness memory checkpoint; identical work each launch).
struct StreamBundle {
    cudaStream_t s2;
    cudaEvent_t e0, e1;
    cudaEvent_t fa[3], fb[3];
    StreamBundle() {
        cudaStreamCreateWithFlags(&s2, cudaStreamNonBlocking);
        cudaEventCreateWithFlags(&e0, cudaEventDisableTiming);
        cudaEventCreateWithFlags(&e1, cudaEventDisableTiming);
        for (int i = 0; i < 3; i++) {
            cudaEventCreateWithFlags(&fa[i], cudaEventDisableTiming);
            cudaEventCreateWithFlags(&fb[i], cudaEventDisableTiming);
        }
    }
};
static StreamBundle g_sb;

// ---------------- helpers ----------------

__device__ __forceinline__ void mma_f16(float* d,
    uint32_t a0, uint32_t a1, uint32_t a2, uint32_t a3,
    uint32_t b0, uint32_t b1)
{
    asm volatile(
        "mma.sync.aligned.m16n8k16.row.col.f32.f16.f16.f32 "
        "{%0,%1,%2,%3}, {%4,%5,%6,%7}, {%8,%9}, {%0,%1,%2,%3};\n"
        : "+f"(d[0]), "+f"(d[1]), "+f"(d[2]), "+f"(d[3])
        : "r"(a0), "r"(a1), "r"(a2), "r"(a3), "r"(b0), "r"(b1));
}

__device__ __forceinline__ void cp_async16(void* smem_p, const void* gmem, bool pred)
{
    uint32_t s = (uint32_t)__cvta_generic_to_shared(smem_p);
    int sz = pred ? 16 : 0;
    asm volatile("cp.async.cg.shared.global [%0], [%1], 16, %2;\n"
                 :: "r"(s), "l"(gmem), "r"(sz));
}
__device__ __forceinline__ void cp_commit() {
    asm volatile("cp.async.commit_group;\n");
}
template <int N_>
__device__ __forceinline__ void cp_wait() {
    asm volatile("cp.async.wait_group %0;\n" :: "n"(N_));
}

// ---------------- conversion ----------------

__global__ void __launch_bounds__(256) convert_w_kernel(
    const float* __restrict__ fw, const float* __restrict__ wrel,
    const float* __restrict__ wroot, __half* __restrict__ Wh)
{
    int idx = blockIdx.x * 256 + threadIdx.x;
    if (idx >= 7 * D * D) return;
    int s = idx >> 14;
    int r = idx & 16383;
    int k = r >> 7;
    int n = r & 127;
    const float* srcm = (s == 0) ? fw
                      : (s < 4)  ? wrel + (size_t)(s - 1) * D * D
                                 : wroot + (size_t)(s - 4) * D * D;
    Wh[(size_t)s * D * D + n * D + k] = __float2half(srcm[k * D + n]);
}

__global__ void __launch_bounds__(256) convert_x_kernel(
    const float* __restrict__ x, __half* __restrict__ Xh, int n4)
{
    int i = blockIdx.x * 256 + threadIdx.x;
    if (i >= n4) return;
    float4 v = ((const float4*)x)[i];
    uint2 o;
    *(__half2*)&o.x = __floats2half2_rn(v.x, v.y);
    *(__half2*)&o.y = __floats2half2_rn(v.z, v.w);
    ((uint2*)Xh)[i] = o;
}

// ---------------- CSR build ----------------

__global__ void __launch_bounds__(256) zero_int_kernel(int* __restrict__ p, int n) {
    int i = blockIdx.x * blockDim.x + threadIdx.x;
    for (; i < n; i += gridDim.x * blockDim.x) p[i] = 0;
}

__global__ void __launch_bounds__(256) hist_rank_kernel(
    const int* __restrict__ dst, int* __restrict__ cnt,
    int* __restrict__ rank, int E)
{
    int i = blockIdx.x * blockDim.x + threadIdx.x;
    for (; i < E; i += gridDim.x * blockDim.x)
        rank[i] = atomicAdd(&cnt[dst[i]], 1);
}

__global__ void __launch_bounds__(1024) scan1_kernel(
    const int* __restrict__ cnt, int* __restrict__ row_ptr,
    int* __restrict__ bsum, int n)
{
    __shared__ int warp_sums[32];
    int tid = threadIdx.x;
    int i = blockIdx.x * 1024 + tid;
    int lane = tid & 31, w = tid >> 5;

    int v = (i < n) ? cnt[i] : 0;
    int incl = v;
    #pragma unroll
    for (int o = 1; o < 32; o <<= 1) {
        int t = __shfl_up_sync(~0u, incl, o);
        if (lane >= o) incl += t;
    }
    if (lane == 31) warp_sums[w] = incl;
    __syncthreads();
    if (w == 0) {
        int s = warp_sums[lane];
        #pragma unroll
        for (int o = 1; o < 32; o <<= 1) {
            int t = __shfl_up_sync(~0u, s, o);
            if (lane >= o) s += t;
        }
        warp_sums[lane] = s;
    }
    __syncthreads();

    int excl = incl - v + (w > 0 ? warp_sums[w - 1] : 0);
    if (i < n) row_ptr[i] = excl;
    if (tid == 1023) bsum[blockIdx.x] = excl + v;
}

__global__ void __launch_bounds__(64) scan2_kernel(
    const int* __restrict__ bsum, int* __restrict__ bofs,
    int* __restrict__ row_ptr, int nblocks, int n)
{
    __shared__ int sh[64];
    int tid = threadIdx.x;
    sh[tid] = (tid < nblocks) ? bsum[tid] : 0;
    __syncthreads();
    if (tid == 0) {
        int run = 0;
        for (int b = 0; b < nblocks; b++) {
            bofs[b] = run;
            run += sh[b];
        }
        row_ptr[n] = run;
    }
}

__global__ void __launch_bounds__(1024) scan3_kernel(
    int* __restrict__ row_ptr, const int* __restrict__ bofs, int n)
{
    int i = blockIdx.x * 1024 + threadIdx.x;
    if (i >= n) return;
    row_ptr[i] += bofs[blockIdx.x];
}

__global__ void __launch_bounds__(256) fill_kernel(
    const int* __restrict__ src, const int* __restrict__ dst,
    const int* __restrict__ rank, const int* __restrict__ row_ptr,
    int* __restrict__ adj, int E)
{
    int i = blockIdx.x * blockDim.x + threadIdx.x;
    for (; i < E; i += gridDim.x * blockDim.x)
        adj[__ldg(row_ptr + dst[i]) + rank[i]] = src[i];
}

// ---------------- gather-aggregate (fp16 in/out, fp32 sums) ----------------

__global__ void __launch_bounds__(256) aggregate_kernel(
    const __half* __restrict__ Ht, const int* __restrict__ row_ptr,
    const int* __restrict__ adj, __half* __restrict__ AGG, int N)
{
    int node = (blockIdx.x * blockDim.x + threadIdx.x) >> 5;
    int lane = threadIdx.x & 31;
    if (node >= N) return;
    int beg = __ldg(row_ptr + node);
    int end = __ldg(row_ptr + node + 1);

    float4 acc = make_float4(0.f, 0.f, 0.f, 0.f);
    int e = beg;
    for (; e + 4 <= end; e += 4) {
        int s0 = __ldg(adj + e + 0);
        int s1 = __ldg(adj + e + 1);
        int s2 = __ldg(adj + e + 2);
        int s3 = __ldg(adj + e + 3);
        uint2 u0 = __ldg((const uint2*)(Ht + (size_t)s0 * D) + lane);
        uint2 u1 = __ldg((const uint2*)(Ht + (size_t)s1 * D) + lane);
        uint2 u2 = __ldg((const uint2*)(Ht + (size_t)s2 * D) + lane);
        uint2 u3 = __ldg((const uint2*)(Ht + (size_t)s3 * D) + lane);
        #pragma unroll
        for (int j = 0; j < 4; j++) {
            uint2 u = j == 0 ? u0 : j == 1 ? u1 : j == 2 ? u2 : u3;
            float2 lo = __half22float2(*(__half2*)&u.x);
            float2 hi = __half22float2(*(__half2*)&u.y);
            acc.x += lo.x; acc.y += lo.y; acc.z += hi.x; acc.w += hi.y;
        }
    }
    for (; e < end; e++) {
        int s = __ldg(adj + e);
        uint2 u = __ldg((const uint2*)(Ht + (size_t)s * D) + lane);
        float2 lo = __half22float2(*(__half2*)&u.x);
        float2 hi = __half22float2(*(__half2*)&u.y);
        acc.x += lo.x; acc.y += lo.y; acc.z += hi.x; acc.w += hi.y;
    }
    uint2 o;
    *(__half2*)&o.x = __floats2half2_rn(acc.x, acc.y);
    *(__half2*)&o.y = __floats2half2_rn(acc.z, acc.w);
    ((uint2*)(AGG + (size_t)node * D))[lane] = o;
}

// ---------------- fp16 GEMM (single-term, 3-stage cp.async) ----------------
// Modes:
//   ADD_P: accumulate P (fp32 partial) in epilogue
//   BIAS : add bias
//   RESID: relu + H residual
//   WRITE_RT: write fp16 copy of output

#define SKH 40
#define TILE_H (128 * SKH)
#define STAGE_H (2 * TILE_H)
#define GEMM16_SMEM (3 * STAGE_H * 2)

template <bool ADD_P, bool BIAS, bool RESID, bool WRITE_RT>
__global__ void __launch_bounds__(256, 2) gemm_f16(
    const __half* __restrict__ A1, const __half* __restrict__ W1,
    const float* __restrict__ P, const float* __restrict__ bias,
    const float* __restrict__ Hres,
    float* __restrict__ out, __half* __restrict__ OutRt, int N)
{
    extern __shared__ __align__(16) __half smh[];

    int tid = threadIdx.x;
    int lane = tid & 31, w = tid >> 5;
    int warp_m = w & 3;
    int warp_n = w >> 2;
    int g = lane >> 2, tg = lane & 3;
    int row0 = blockIdx.x * 128;

    float acc[2][8][4];
    #pragma unroll
    for (int mf = 0; mf < 2; mf++)
        #pragma unroll
        for (int nf = 0; nf < 8; nf++)
            #pragma unroll
            for (int c = 0; c < 4; c++) acc[mf][nf][c] = 0.f;

    const int NC = 4;

    auto prefetch = [&](int c, int buf) {
        int koff = c * 32;
        __half* base = smh + buf * STAGE_H;
        #pragma unroll
        for (int i = 0; i < 2; i++) {
            int idx = tid + i * 256;
            int r = idx >> 2, u = idx & 3;
            int gr = row0 + r;
            cp_async16(base + r * SKH + u * 8,
                       A1 + (size_t)gr * D + koff + u * 8, gr < N);
            cp_async16(base + TILE_H + r * SKH + u * 8,
                       W1 + (size_t)r * D + koff + u * 8, true);
        }
        cp_commit();
    };

    prefetch(0, 0);
    prefetch(1, 1);

    #pragma unroll 1
    for (int c = 0; c < NC; c++) {
        if (c + 1 < NC) cp_wait<1>(); else cp_wait<0>();
        __syncthreads();
        if (c + 2 < NC) prefetch(c + 2, (c + 2) % 3);

        const uint32_t* sa = (const uint32_t*)(smh + (c % 3) * STAGE_H);
        const uint32_t* sb = sa + TILE_H / 2;

        #pragma unroll
        for (int ks = 0; ks < 2; ks++) {
            uint32_t bfr[8][2];
            #pragma unroll
            for (int nf = 0; nf < 8; nf++) {
                int n = warp_n * 64 + nf * 8 + g;
                bfr[nf][0] = sb[n * 20 + ks * 8 + tg];
                bfr[nf][1] = sb[n * 20 + ks * 8 + tg + 4];
            }
            #pragma unroll
            for (int mf = 0; mf < 2; mf++) {
                int r0 = warp_m * 32 + mf * 16 + g;
                uint32_t a0 = sa[r0 * 20 + ks * 8 + tg];
                uint32_t a1 = sa[(r0 + 8) * 20 + ks * 8 + tg];
                uint32_t a2 = sa[r0 * 20 + ks * 8 + tg + 4];
                uint32_t a3 = sa[(r0 + 8) * 20 + ks * 8 + tg + 4];
                #pragma unroll
                for (int nf = 0; nf < 8; nf++)
                    mma_f16(acc[mf][nf], a0, a1, a2, a3,
                            bfr[nf][0], bfr[nf][1]);
            }
        }
    }

    __syncthreads();

    #pragma unroll
    for (int mf = 0; mf < 2; mf++) {
        #pragma unroll
        for (int half = 0; half < 2; half++) {
            int row = row0 + warp_m * 32 + mf * 16 + g + half * 8;
            if (row >= N) continue;
            #pragma unroll
            for (int nf = 0; nf < 8; nf++) {
                int col = warp_n * 64 + nf * 8 + tg * 2;
                float cx = acc[mf][nf][half * 2 + 0];
                float cy = acc[mf][nf][half * 2 + 1];
                if (ADD_P) {
                    float2 p2 = *(const float2*)(P + (size_t)row * D + col);
                    cx += p2.x;
                    cy += p2.y;
                }
                if (BIAS) {
                    cx += __ldg(bias + col);
                    cy += __ldg(bias + col + 1);
                }
                if (RESID) {
                    float2 h2 = *(const float2*)(Hres + (size_t)row * D + col);
                    cx = fmaxf(cx, 0.f) + h2.x;
                    cy = fmaxf(cy, 0.f) + h2.y;
                }
                *(float2*)(out + (size_t)row * D + col) = make_float2(cx, cy);
                if (WRITE_RT) {
                    *(__half2*)(OutRt + (size_t)row * D + col) =
                        __floats2half2_rn(cx, cy);
                }
            }
        }
    }
}

// ---------------- launch ----------------

extern "C" void kernel_launch(void* const* d_in, const int* in_sizes, int n_in,
                              void* d_out, int out_size)
{
    const float* x       = (const float*)d_in[0];
    const int*   ei      = (const int*)  d_in[1];
    const float* in_fc_w = (const float*)d_in[2];
    const float* in_fc_b = (const float*)d_in[3];
    const float* w_rel   = (const float*)d_in[4];
    const float* b_rel   = (const float*)d_in[5];
    const float* w_root  = (const float*)d_in[6];

    int N = in_sizes[0] / D;
    int E = in_sizes[1] / 2;
    const int* src = ei;
    const int* dst = ei + E;

    float *H, *P;
    __half *Ht, *AGG, *Wh;
    int *cnt, *row_ptr, *rank, *adj, *bsum, *bofs;
    cudaGetSymbolAddress((void**)&H,       g_H);
    cudaGetSymbolAddress((void**)&P,       g_P);
    cudaGetSymbolAddress((void**)&Ht,      g_Ht);
    cudaGetSymbolAddress((void**)&AGG,     g_AGG);
    cudaGetSymbolAddress((void**)&Wh,      g_Wh);
    cudaGetSymbolAddress((void**)&cnt,     g_cnt);
    cudaGetSymbolAddress((void**)&row_ptr, g_row_ptr);
    cudaGetSymbolAddress((void**)&rank,    g_rank);
    cudaGetSymbolAddress((void**)&adj,     g_adj);
    cudaGetSymbolAddress((void**)&bsum,    g_bsum);
    cudaGetSymbolAddress((void**)&bofs,    g_bofs);

    cudaFuncSetAttribute((const void*)gemm_f16<false, true, false, true>,
        cudaFuncAttributeMaxDynamicSharedMemorySize, GEMM16_SMEM);
    cudaFuncSetAttribute((const void*)gemm_f16<false, false, false, false>,
        cudaFuncAttributeMaxDynamicSharedMemorySize, GEMM16_SMEM);
    cudaFuncSetAttribute((const void*)gemm_f16<true, true, true, true>,
        cudaFuncAttributeMaxDynamicSharedMemorySize, GEMM16_SMEM);
    cudaFuncSetAttribute((const void*)gemm_f16<true, true, true, false>,
        cudaFuncAttributeMaxDynamicSharedMemorySize, GEMM16_SMEM);

    int gblocks = (N + 127) / 128;
    int eblocks = (E + 255) / 256;
    int ablocks = (N * 32 + 255) / 256;
    int sblocks = (N + 1023) / 1024;
    int xblocks = (N * D / 4 + 255) / 256;

    cudaStream_t s2 = g_sb.s2;

    // Head fork: CSR build on s2, concurrent with conversions + in_fc.
    cudaEventRecord(g_sb.e0, 0);
    cudaStreamWaitEvent(s2, g_sb.e0, 0);

    zero_int_kernel<<<(N + 255) / 256, 256, 0, s2>>>(cnt, N);
    hist_rank_kernel<<<eblocks, 256, 0, s2>>>(dst, cnt, rank, E);
    scan1_kernel<<<sblocks, 1024, 0, s2>>>(cnt, row_ptr, bsum, N);
    scan2_kernel<<<1, 64, 0, s2>>>(bsum, bofs, row_ptr, sblocks, N);
    scan3_kernel<<<sblocks, 1024, 0, s2>>>(row_ptr, bofs, N);
    fill_kernel<<<eblocks, 256, 0, s2>>>(src, dst, rank, row_ptr, adj, E);
    cudaEventRecord(g_sb.e1, s2);

    // Main: conversions + in_fc (h = x@W + b; writes H fp32 + Ht fp16)
    convert_w_kernel<<<(7 * D * D + 255) / 256, 256>>>(in_fc_w, w_rel, w_root, Wh);
    convert_x_kernel<<<xblocks, 256>>>(x, AGG, N * D / 4);
    gemm_f16<false, true, false, true><<<gblocks, 256, GEMM16_SMEM>>>(
        AGG, Wh, nullptr, in_fc_b, nullptr, H, Ht, N);

    // Join: layer loop needs CSR + Ht.
    cudaStreamWaitEvent(0, g_sb.e1, 0);

    for (int l = 0; l < 3; l++) {
        const __half* W1 = Wh + (size_t)(1 + l) * D * D;   // w_rel
        const __half* W2 = Wh + (size_t)(4 + l) * D * D;   // w_root

        // Fork: aggregate (s2) || root GEMM P = Ht@W2 (main).
        cudaEventRecord(g_sb.fa[l], 0);
        cudaStreamWaitEvent(s2, g_sb.fa[l], 0);
        aggregate_kernel<<<ablocks, 256, 0, s2>>>(Ht, row_ptr, adj, AGG, N);
        cudaEventRecord(g_sb.fb[l], s2);

        gemm_f16<false, false, false, false><<<gblocks, 256, GEMM16_SMEM>>>(
            Ht, W2, nullptr, nullptr, nullptr, P, nullptr, N);

        // Join, then rel GEMM: out = relu(AGG@W1 + P + bias) + H.
        cudaStreamWaitEvent(0, g_sb.fb[l], 0);
        if (l < 2) {
            gemm_f16<true, true, true, true><<<gblocks, 256, GEMM16_SMEM>>>(
                AGG, W1, P, b_rel + (size_t)l * D, H, H, Ht, N);
        } else {
            gemm_f16<true, true, true, false><<<gblocks, 256, GEMM16_SMEM>>>(
                AGG, W1, P, b_rel + (size_t)l * D, H, (float*)d_out, nullptr, N);
        }
    }
}

// round 17
// speedup vs baseline: 1.1878x; 1.1878x over previous
#include <cuda_runtime.h>
#include <cuda_fp16.h>
#include <cstdint>

#define D 128
#define MAXN 50000
#define MAXE 800000

// Scratch (allocation-free)
__device__ __half g_Ht[MAXN * D];     // fp16 H (residual carry + GEMM A + gather src)
__device__ __half g_AGG[MAXN * D];    // fp16 aggregate (also fp16 x for in_fc)
__device__ __half g_Wh[7 * D * D];    // fp16 weights, transposed [n][k]
__device__ int g_cnt[MAXN];
__device__ int g_row_ptr[MAXN + 1];
__device__ int g_rank[MAXE];
__device__ int g_adj[MAXE];
__device__ int g_sflag[64];           // packed (prefix+1) per scan block; 0 = not ready

// Side stream + events, created at static-init (host objects; before the
// harness memory checkpoint; identical work each launch).
struct StreamBundle {
    cudaStream_t s2;
    cudaEvent_t e0, e1;
    StreamBundle() {
        cudaStreamCreateWithFlags(&s2, cudaStreamNonBlocking);
        cudaEventCreateWithFlags(&e0, cudaEventDisableTiming);
        cudaEventCreateWithFlags(&e1, cudaEventDisableTiming);
    }
};
static StreamBundle g_sb;

// ---------------- helpers ----------------

__device__ __forceinline__ void mma_f16(float* d,
    uint32_t a0, uint32_t a1, uint32_t a2, uint32_t a3,
    uint32_t b0, uint32_t b1)
{
    asm volatile(
        "mma.sync.aligned.m16n8k16.row.col.f32.f16.f16.f32 "
        "{%0,%1,%2,%3}, {%4,%5,%6,%7}, {%8,%9}, {%0,%1,%2,%3};\n"
        : "+f"(d[0]), "+f"(d[1]), "+f"(d[2]), "+f"(d[3])
        : "r"(a0), "r"(a1), "r"(a2), "r"(a3), "r"(b0), "r"(b1));
}

__device__ __forceinline__ void cp_async16(void* smem_p, const void* gmem, bool pred)
{
    uint32_t s = (uint32_t)__cvta_generic_to_shared(smem_p);
    int sz = pred ? 16 : 0;
    asm volatile("cp.async.cg.shared.global [%0], [%1], 16, %2;\n"
                 :: "r"(s), "l"(gmem), "r"(sz));
}
__device__ __forceinline__ void cp_commit() {
    asm volatile("cp.async.commit_group;\n");
}
template <int N_>
__device__ __forceinline__ void cp_wait() {
    asm volatile("cp.async.wait_group %0;\n" :: "n"(N_));
}

// ---------------- conversion ----------------

__global__ void __launch_bounds__(256) convert_w_kernel(
    const float* __restrict__ fw, const float* __restrict__ wrel,
    const float* __restrict__ wroot, __half* __restrict__ Wh)
{
    int idx = blockIdx.x * 256 + threadIdx.x;
    if (idx >= 7 * D * D) return;
    int s = idx >> 14;
    int r = idx & 16383;
    int k = r >> 7;
    int n = r & 127;
    const float* srcm = (s == 0) ? fw
                      : (s < 4)  ? wrel + (size_t)(s - 1) * D * D
                                 : wroot + (size_t)(s - 4) * D * D;
    Wh[(size_t)s * D * D + n * D + k] = __float2half(srcm[k * D + n]);
}

__global__ void __launch_bounds__(256) convert_x_kernel(
    const float* __restrict__ x, __half* __restrict__ Xh, int n4)
{
    int i = blockIdx.x * 256 + threadIdx.x;
    if (i >= n4) return;
    float4 v = ((const float4*)x)[i];
    uint2 o;
    *(__half2*)&o.x = __floats2half2_rn(v.x, v.y);
    *(__half2*)&o.y = __floats2half2_rn(v.z, v.w);
    ((uint2*)Xh)[i] = o;
}

// ---------------- CSR build ----------------

// zero cnt[n] and the scan flags
__global__ void __launch_bounds__(256) zero2_kernel(
    int* __restrict__ cnt, int* __restrict__ flags, int n)
{
    int i = blockIdx.x * blockDim.x + threadIdx.x;
    if (blockIdx.x == 0 && threadIdx.x < 64) flags[threadIdx.x] = 0;
    for (; i < n; i += gridDim.x * blockDim.x) cnt[i] = 0;
}

__global__ void __launch_bounds__(256) hist_rank_kernel(
    const int* __restrict__ dst, int* __restrict__ cnt,
    int* __restrict__ rank, int E)
{
    int i = blockIdx.x * blockDim.x + threadIdx.x;
    for (; i < E; i += gridDim.x * blockDim.x)
        rank[i] = atomicAdd(&cnt[dst[i]], 1);
}

// Single-pass scan with decoupled lookback (49 blocks -> single wave).
// g_sflag[b] packs (inclusive-prefix-of-block-sums + 1); 0 = not published.
__global__ void __launch_bounds__(1024) scan_fused_kernel(
    const int* __restrict__ cnt, int* __restrict__ row_ptr,
    int* __restrict__ sflag, int n)
{
    __shared__ int warp_sums[32];
    __shared__ int sh_base;
    int tid = threadIdx.x;
    int b = blockIdx.x;
    int i = b * 1024 + tid;
    int lane = tid & 31, w = tid >> 5;

    int v = (i < n) ? cnt[i] : 0;
    int incl = v;
    #pragma unroll
    for (int o = 1; o < 32; o <<= 1) {
        int t = __shfl_up_sync(~0u, incl, o);
        if (lane >= o) incl += t;
    }
    if (lane == 31) warp_sums[w] = incl;
    __syncthreads();
    if (w == 0) {
        int s = warp_sums[lane];
        #pragma unroll
        for (int o = 1; o < 32; o <<= 1) {
            int t = __shfl_up_sync(~0u, s, o);
            if (lane >= o) s += t;
        }
        warp_sums[lane] = s;
    }
    __syncthreads();

    if (tid == 0) {
        int total = warp_sums[31];
        int base = 0;
        if (b > 0) {
            int p;
            do { p = atomicAdd(&sflag[b - 1], 0); } while (p == 0);
            base = p - 1;
        }
        atomicExch(&sflag[b], base + total + 1);
        sh_base = base;
        if (b == gridDim.x - 1) row_ptr[n] = base + total;
    }
    __syncthreads();

    int excl = incl - v + (w > 0 ? warp_sums[w - 1] : 0) + sh_base;
    if (i < n) row_ptr[i] = excl;
}

__global__ void __launch_bounds__(256) fill_kernel(
    const int* __restrict__ src, const int* __restrict__ dst,
    const int* __restrict__ rank, const int* __restrict__ row_ptr,
    int* __restrict__ adj, int E)
{
    int i = blockIdx.x * blockDim.x + threadIdx.x;
    for (; i < E; i += gridDim.x * blockDim.x)
        adj[__ldg(row_ptr + dst[i]) + rank[i]] = src[i];
}

// ---------------- gather-aggregate (fp16 in/out, fp32 sums) ----------------

__global__ void __launch_bounds__(256) aggregate_kernel(
    const __half* __restrict__ Ht, const int* __restrict__ row_ptr,
    const int* __restrict__ adj, __half* __restrict__ AGG, int N)
{
    int node = (blockIdx.x * blockDim.x + threadIdx.x) >> 5;
    int lane = threadIdx.x & 31;
    if (node >= N) return;
    int beg = __ldg(row_ptr + node);
    int end = __ldg(row_ptr + node + 1);

    float4 acc = make_float4(0.f, 0.f, 0.f, 0.f);
    int e = beg;
    for (; e + 4 <= end; e += 4) {
        int s0 = __ldg(adj + e + 0);
        int s1 = __ldg(adj + e + 1);
        int s2 = __ldg(adj + e + 2);
        int s3 = __ldg(adj + e + 3);
        uint2 u0 = __ldg((const uint2*)(Ht + (size_t)s0 * D) + lane);
        uint2 u1 = __ldg((const uint2*)(Ht + (size_t)s1 * D) + lane);
        uint2 u2 = __ldg((const uint2*)(Ht + (size_t)s2 * D) + lane);
        uint2 u3 = __ldg((const uint2*)(Ht + (size_t)s3 * D) + lane);
        #pragma unroll
        for (int j = 0; j < 4; j++) {
            uint2 u = j == 0 ? u0 : j == 1 ? u1 : j == 2 ? u2 : u3;
            float2 lo = __half22float2(*(__half2*)&u.x);
            float2 hi = __half22float2(*(__half2*)&u.y);
            acc.x += lo.x; acc.y += lo.y; acc.z += hi.x; acc.w += hi.y;
        }
    }
    for (; e < end; e++) {
        int s = __ldg(adj + e);
        uint2 u = __ldg((const uint2*)(Ht + (size_t)s * D) + lane);
        float2 lo = __half22float2(*(__half2*)&u.x);
        float2 hi = __half22float2(*(__half2*)&u.y);
        acc.x += lo.x; acc.y += lo.y; acc.z += hi.x; acc.w += hi.y;
    }
    uint2 o;
    *(__half2*)&o.x = __floats2half2_rn(acc.x, acc.y);
    *(__half2*)&o.y = __floats2half2_rn(acc.z, acc.w);
    ((uint2*)(AGG + (size_t)node * D))[lane] = o;
}

// ---------------- fp16 GEMM (single/dual term, 3-stage cp.async) ----------
// in_fc      : DUAL=0 RESID=0 F32OUT=0 -> Ht = x@W + b       (fp16 out)
// layer 0,1  : DUAL=1 RESID=1 F32OUT=0 -> Ht = relu(...)+Ht  (fp16 carry)
// layer 2    : DUAL=1 RESID=1 F32OUT=1 -> d_out = relu(...)+Ht (fp32 out)

#define SKH 40
#define TILE_H (128 * SKH)
#define STAGE_H (2 * TILE_H)
#define GEMM16_SMEM (3 * STAGE_H * 2)

template <bool DUAL, bool RESID, bool F32OUT>
__global__ void __launch_bounds__(256, 2) gemm_f16(
    const __half* __restrict__ A1, const __half* __restrict__ W1,
    const __half* __restrict__ A2, const __half* __restrict__ W2,
    const float* __restrict__ bias, const __half* __restrict__ HtRes,
    float* __restrict__ outF, __half* __restrict__ outH, int N)
{
    extern __shared__ __align__(16) __half smh[];

    int tid = threadIdx.x;
    int lane = tid & 31, w = tid >> 5;
    int warp_m = w & 3;
    int warp_n = w >> 2;
    int g = lane >> 2, tg = lane & 3;
    int row0 = blockIdx.x * 128;

    float acc[2][8][4];
    #pragma unroll
    for (int mf = 0; mf < 2; mf++)
        #pragma unroll
        for (int nf = 0; nf < 8; nf++)
            #pragma unroll
            for (int c = 0; c < 4; c++) acc[mf][nf][c] = 0.f;

    const int NC = DUAL ? 8 : 4;

    auto prefetch = [&](int c, int buf) {
        int t = c >> 2;
        int koff = (c & 3) * 32;
        const __half* Ag = (DUAL && t) ? A2 : A1;
        const __half* Bg = (DUAL && t) ? W2 : W1;
        __half* base = smh + buf * STAGE_H;
        #pragma unroll
        for (int i = 0; i < 2; i++) {
            int idx = tid + i * 256;
            int r = idx >> 2, u = idx & 3;
            int gr = row0 + r;
            cp_async16(base + r * SKH + u * 8,
                       Ag + (size_t)gr * D + koff + u * 8, gr < N);
            cp_async16(base + TILE_H + r * SKH + u * 8,
                       Bg + (size_t)r * D + koff + u * 8, true);
        }
        cp_commit();
    };

    prefetch(0, 0);
    prefetch(1, 1);

    #pragma unroll 1
    for (int c = 0; c < NC; c++) {
        if (c + 1 < NC) cp_wait<1>(); else cp_wait<0>();
        __syncthreads();
        if (c + 2 < NC) prefetch(c + 2, (c + 2) % 3);

        const uint32_t* sa = (const uint32_t*)(smh + (c % 3) * STAGE_H);
        const uint32_t* sb = sa + TILE_H / 2;

        #pragma unroll
        for (int ks = 0; ks < 2; ks++) {
            uint32_t bfr[8][2];
            #pragma unroll
            for (int nf = 0; nf < 8; nf++) {
                int n = warp_n * 64 + nf * 8 + g;
                bfr[nf][0] = sb[n * 20 + ks * 8 + tg];
                bfr[nf][1] = sb[n * 20 + ks * 8 + tg + 4];
            }
            #pragma unroll
            for (int mf = 0; mf < 2; mf++) {
                int r0 = warp_m * 32 + mf * 16 + g;
                uint32_t a0 = sa[r0 * 20 + ks * 8 + tg];
                uint32_t a1 = sa[(r0 + 8) * 20 + ks * 8 + tg];
                uint32_t a2 = sa[r0 * 20 + ks * 8 + tg + 4];
                uint32_t a3 = sa[(r0 + 8) * 20 + ks * 8 + tg + 4];
                #pragma unroll
                for (int nf = 0; nf < 8; nf++)
                    mma_f16(acc[mf][nf], a0, a1, a2, a3,
                            bfr[nf][0], bfr[nf][1]);
            }
        }
    }

    __syncthreads();

    #pragma unroll
    for (int mf = 0; mf < 2; mf++) {
        #pragma unroll
        for (int half = 0; half < 2; half++) {
            int row = row0 + warp_m * 32 + mf * 16 + g + half * 8;
            if (row >= N) continue;
            #pragma unroll
            for (int nf = 0; nf < 8; nf++) {
                int col = warp_n * 64 + nf * 8 + tg * 2;
                float cx = acc[mf][nf][half * 2 + 0] + __ldg(bias + col);
                float cy = acc[mf][nf][half * 2 + 1] + __ldg(bias + col + 1);
                if (RESID) {
                    __half2 h2 = *(const __half2*)(HtRes + (size_t)row * D + col);
                    float2 hf = __half22float2(h2);
                    cx = fmaxf(cx, 0.f) + hf.x;
                    cy = fmaxf(cy, 0.f) + hf.y;
                }
                if (F32OUT) {
                    *(float2*)(outF + (size_t)row * D + col) = make_float2(cx, cy);
                } else {
                    *(__half2*)(outH + (size_t)row * D + col) =
                        __floats2half2_rn(cx, cy);
                }
            }
        }
    }
}

// ---------------- launch ----------------

extern "C" void kernel_launch(void* const* d_in, const int* in_sizes, int n_in,
                              void* d_out, int out_size)
{
    const float* x       = (const float*)d_in[0];
    const int*   ei      = (const int*)  d_in[1];
    const float* in_fc_w = (const float*)d_in[2];
    const float* in_fc_b = (const float*)d_in[3];
    const float* w_rel   = (const float*)d_in[4];
    const float* b_rel   = (const float*)d_in[5];
    const float* w_root  = (const float*)d_in[6];

    int N = in_sizes[0] / D;
    int E = in_sizes[1] / 2;
    const int* src = ei;
    const int* dst = ei + E;

    __half *Ht, *AGG, *Wh;
    int *cnt, *row_ptr, *rank, *adj, *sflag;
    cudaGetSymbolAddress((void**)&Ht,      g_Ht);
    cudaGetSymbolAddress((void**)&AGG,     g_AGG);
    cudaGetSymbolAddress((void**)&Wh,      g_Wh);
    cudaGetSymbolAddress((void**)&cnt,     g_cnt);
    cudaGetSymbolAddress((void**)&row_ptr, g_row_ptr);
    cudaGetSymbolAddress((void**)&rank,    g_rank);
    cudaGetSymbolAddress((void**)&adj,     g_adj);
    cudaGetSymbolAddress((void**)&sflag,   g_sflag);

    cudaFuncSetAttribute((const void*)gemm_f16<false, false, false>,
        cudaFuncAttributeMaxDynamicSharedMemorySize, GEMM16_SMEM);
    cudaFuncSetAttribute((const void*)gemm_f16<true, true, false>,
        cudaFuncAttributeMaxDynamicSharedMemorySize, GEMM16_SMEM);
    cudaFuncSetAttribute((const void*)gemm_f16<true, true, true>,
        cudaFuncAttributeMaxDynamicSharedMemorySize, GEMM16_SMEM);

    int gblocks = (N + 127) / 128;
    int eblocks = (E + 255) / 256;
    int ablocks = (N * 32 + 255) / 256;
    int sblocks = (N + 1023) / 1024;
    int xblocks = (N * D / 4 + 255) / 256;

    cudaStream_t s2 = g_sb.s2;

    // Head fork: CSR build on s2, concurrent with conversions + in_fc.
    cudaEventRecord(g_sb.e0, 0);
    cudaStreamWaitEvent(s2, g_sb.e0, 0);

    zero2_kernel<<<(N + 255) / 256, 256, 0, s2>>>(cnt, sflag, N);
    hist_rank_kernel<<<eblocks, 256, 0, s2>>>(dst, cnt, rank, E);
    scan_fused_kernel<<<sblocks, 1024, 0, s2>>>(cnt, row_ptr, sflag, N);
    fill_kernel<<<eblocks, 256, 0, s2>>>(src, dst, rank, row_ptr, adj, E);
    cudaEventRecord(g_sb.e1, s2);

    // Main: conversions + in_fc (Ht = x@W + b, fp16)
    convert_w_kernel<<<(7 * D * D + 255) / 256, 256>>>(in_fc_w, w_rel, w_root, Wh);
    convert_x_kernel<<<xblocks, 256>>>(x, AGG, N * D / 4);
    gemm_f16<false, false, false><<<gblocks, 256, GEMM16_SMEM>>>(
        AGG, Wh, nullptr, nullptr, in_fc_b, nullptr, nullptr, Ht, N);

    // Join: layer loop needs CSR + Ht.
    cudaStreamWaitEvent(0, g_sb.e1, 0);

    for (int l = 0; l < 3; l++) {
        aggregate_kernel<<<ablocks, 256>>>(Ht, row_ptr, adj, AGG, N);
        const __half* W1 = Wh + (size_t)(1 + l) * D * D;
        const __half* W2 = Wh + (size_t)(4 + l) * D * D;
        if (l < 2) {
            gemm_f16<true, true, false><<<gblocks, 256, GEMM16_SMEM>>>(
                AGG, W1, Ht, W2, b_rel + (size_t)l * D, Ht, nullptr, Ht, N);
        } else {
            gemm_f16<true, true, true><<<gblocks, 256, GEMM16_SMEM>>>(
                AGG, W1, Ht, W2, b_rel + (size_t)l * D, Ht,
                (float*)d_out, nullptr, N);
        }
    }
}